// round 5
// baseline (speedup 1.0000x reference)
#include <cuda_runtime.h>

// MaxFeatBlockDescriptorLayer, fused single launch, "last block finishes":
//   All 128 blocks: coalesced chunk reduction of prob [B,16384,8] -> per-chunk
//   (packed max|~idx, sum) partials per (b,k) in fixed slots, then
//   fence + per-batch counter atomicAdd. The block that observes count ==
//   CHUNKS-1 for its batch immediately reduces all 64 partials for all 8
//   classes and gathers emb[b, argmax_k, :] * mask_k for k=0..7.
//   No spin loop, no waiter blocks -> one less global-latency hop.
//
// argmax tie-break = first index, via packing (bits(v)<<32)|(N_POS-1-n) and
// max (prob >= 0 so float bits are order-monotonic).
//
// Replay-safe: counter reset by the finisher (sole reader, after observing
// CHUNKS-1); partial slots are plain overwrites each run.

#define N_POS    16384
#define N_CLS    8
#define C_DIM    2048
#define TAU      0.3f
#define CHUNKS   64
#define POS_PC   (N_POS / CHUNKS)        // 256
#define NTHREADS 256
#define MAX_B    8

__device__ unsigned long long g_pack[MAX_B * N_CLS * CHUNKS];
__device__ float              g_sum [MAX_B * N_CLS * CHUNKS];
__device__ unsigned int       g_cnt [MAX_B];

__global__ __launch_bounds__(NTHREADS)
void mfbd_fused(const float* __restrict__ emb,
                const float* __restrict__ prob,
                float* __restrict__ out)
{
    const int t    = threadIdx.x;
    const int w    = t >> 5;             // warp id = class id
    const int lane = t & 31;

    __shared__ __align__(16) float sv[POS_PC * N_CLS];   // 8 KB staging
    __shared__ int   s_arg [N_CLS];
    __shared__ float s_mask[N_CLS];
    __shared__ unsigned int s_last;

    const int b     = blockIdx.x / CHUNKS;
    const int chunk = blockIdx.x % CHUNKS;

    // ---------------- Phase 1: chunk reduction ----------------
    const float4* __restrict__ p4 =
        (const float4*)prob + ((size_t)b * N_POS + (size_t)chunk * POS_PC) * 2;

    float4 a0 = __ldg(p4 + t);
    float4 a1 = __ldg(p4 + t + NTHREADS);
    ((float4*)sv)[t]            = a0;
    ((float4*)sv)[t + NTHREADS] = a1;
    __syncthreads();

    unsigned long long best = 0ULL;
    float s = 0.0f;

    #pragma unroll
    for (int i = 0; i < POS_PC / 32; ++i) {       // 8 positions per lane
        const int p = lane + i * 32;
        const float v = sv[p * N_CLS + w];
        s += v;
        const unsigned comp = (unsigned)(N_POS - 1 - (chunk * POS_PC + p));
        const unsigned long long pk =
            ((unsigned long long)__float_as_uint(v) << 32) | comp;
        best = best > pk ? best : pk;
    }

    #pragma unroll
    for (int off = 16; off > 0; off >>= 1) {
        const unsigned long long ob = __shfl_down_sync(0xffffffffu, best, off);
        best = best > ob ? best : ob;
        s += __shfl_down_sync(0xffffffffu, s, off);
    }

    if (lane == 0) {
        const int slot = (b * N_CLS + w) * CHUNKS + chunk;
        g_pack[slot] = best;
        g_sum[slot]  = s;
    }
    __syncthreads();              // all 8 warps' partials issued

    // ---------------- Arrive; last block per batch continues ----------------
    if (t == 0) {
        __threadfence();          // publish partials
        s_last = atomicAdd(&g_cnt[b], 1u);
    }
    __syncthreads();

    if (s_last != (unsigned)(CHUNKS - 1)) return;   // not the finisher

    // Finisher: all other blocks' partials are visible (their fence + atomic
    // happened-before our atomic returned CHUNKS-1).
    __threadfence();              // acquire

    // ---------------- Phase 2: final reduce (warp w -> class w) -------------
    {
        const int base = (b * N_CLS + w) * CHUNKS;
        unsigned long long p0 = g_pack[base + lane];
        unsigned long long p1 = g_pack[base + lane + 32];
        float s0 = g_sum[base + lane] + g_sum[base + lane + 32];
        unsigned long long bp = p0 > p1 ? p0 : p1;

        #pragma unroll
        for (int off = 16; off > 0; off >>= 1) {
            const unsigned long long ob = __shfl_down_sync(0xffffffffu, bp, off);
            bp = bp > ob ? bp : ob;
            s0 += __shfl_down_sync(0xffffffffu, s0, off);
        }
        if (lane == 0) {
            s_arg [w] = N_POS - 1 - (int)(unsigned)(bp & 0xffffffffu);
            s_mask[w] = (s0 * (1.0f / N_POS) > TAU) ? 1.0f : 0.0f;
        }
    }
    __syncthreads();

    // ---------------- Phase 3: gather 8 rows (16 indep float4/thread) -------
    const float* __restrict__ eb = emb + (size_t)b * N_POS * C_DIM;
    float* __restrict__ ob4 = out + (size_t)b * N_CLS * C_DIM;

    #pragma unroll
    for (int k = 0; k < N_CLS; ++k) {
        const float4* __restrict__ src = (const float4*)(eb + (size_t)s_arg[k] * C_DIM);
        float4* __restrict__ dst = (float4*)(ob4 + (size_t)k * C_DIM);
        const float m = s_mask[k];
        float4 v0 = __ldg(src + t);
        float4 v1 = __ldg(src + t + NTHREADS);
        v0.x *= m; v0.y *= m; v0.z *= m; v0.w *= m;
        v1.x *= m; v1.y *= m; v1.z *= m; v1.w *= m;
        dst[t]            = v0;
        dst[t + NTHREADS] = v1;
    }

    // ---------------- Replay-safe counter reset ----------------
    if (t == 0) {
        g_cnt[b] = 0u;            // sole reader observed CHUNKS-1; safe
        __threadfence();
    }
}

extern "C" void kernel_launch(void* const* d_in, const int* in_sizes, int n_in,
                              void* d_out, int out_size)
{
    const float* emb  = (const float*)d_in[0];
    const float* prob = (const float*)d_in[1];
    float* out = (float*)d_out;

    const int B = in_sizes[0] / (N_POS * C_DIM);   // = 2

    mfbd_fused<<<B * CHUNKS, NTHREADS>>>(emb, prob, out);
}

// round 6
// speedup vs baseline: 1.0179x; 1.0179x over previous
#include <cuda_runtime.h>

// MaxFeatBlockDescriptorLayer, fused single launch, direct-atomic reduction:
//   128 blocks, each reduces one 256-position chunk of prob [B,16384,8]:
//     warp w (class w) -> packed (bits(v)<<32 | N-1-n) atomicMax + sum
//     atomicAdd straight into 16 FINAL slots. No per-chunk partials,
//     no second reduction.
//   Blocks with chunk<8 then spin on a per-batch counter; once all 64 chunks
//   of their batch arrived, they read the final slot and gather
//   emb[b, argmax, :] * mask (16 blocks -> full gather parallelism).
//
// argmax tie-break = first index (comp index monotone decreasing in n).
// Replay-safe: last gather block resets slots (identity 0 for packed max)
// and counters after every reader is done.

#define N_POS    16384
#define N_CLS    8
#define C_DIM    2048
#define TAU      0.3f
#define CHUNKS   64
#define POS_PC   (N_POS / CHUNKS)        // 256
#define NTHREADS 256
#define MAX_B    8

__device__ unsigned long long g_pack[MAX_B * N_CLS];   // final packed max
__device__ float              g_sum [MAX_B * N_CLS];   // final sums
__device__ unsigned int       g_cnt [MAX_B];           // chunks arrived
__device__ unsigned int       g_done;                  // gather blocks done

__global__ __launch_bounds__(NTHREADS)
void mfbd_fused(const float* __restrict__ emb,
                const float* __restrict__ prob,
                float* __restrict__ out)
{
    const int t    = threadIdx.x;
    const int w    = t >> 5;             // warp id = class id
    const int lane = t & 31;

    __shared__ __align__(16) float sv[POS_PC * N_CLS];   // 8 KB staging
    __shared__ int   s_arg;
    __shared__ float s_mask;

    const int b     = blockIdx.x / CHUNKS;
    const int chunk = blockIdx.x % CHUNKS;

    // ---------------- Phase 1: chunk reduction ----------------
    const float4* __restrict__ p4 =
        (const float4*)prob + ((size_t)b * N_POS + (size_t)chunk * POS_PC) * 2;

    float4 a0 = __ldg(p4 + t);
    float4 a1 = __ldg(p4 + t + NTHREADS);
    ((float4*)sv)[t]            = a0;
    ((float4*)sv)[t + NTHREADS] = a1;
    __syncthreads();

    unsigned long long best = 0ULL;
    float s = 0.0f;

    #pragma unroll
    for (int i = 0; i < POS_PC / 32; ++i) {       // 8 positions per lane
        const int p = lane + i * 32;
        const float v = sv[p * N_CLS + w];
        s += v;
        const unsigned comp = (unsigned)(N_POS - 1 - (chunk * POS_PC + p));
        const unsigned long long pk =
            ((unsigned long long)__float_as_uint(v) << 32) | comp;
        best = best > pk ? best : pk;
    }

    #pragma unroll
    for (int off = 16; off > 0; off >>= 1) {
        const unsigned long long ob = __shfl_down_sync(0xffffffffu, best, off);
        best = best > ob ? best : ob;
        s += __shfl_down_sync(0xffffffffu, s, off);
    }

    // Warp leaders: fire-and-forget REDs into the FINAL slots.
    if (lane == 0) {
        const int slot = b * N_CLS + w;
        atomicMax(&g_pack[slot], best);
        atomicAdd(&g_sum[slot], s);
        __threadfence();                  // order REDs before the arrive
    }
    __syncthreads();

    if (t == 0) {
        atomicAdd(&g_cnt[b], 1u);         // arrive
    }

    // Only chunk<8 blocks gather (block for class k = chunk).
    if (chunk >= N_CLS) return;
    const int k = chunk;

    // ---------------- Spin until batch complete ----------------
    if (t == 0) {
        while (atomicAdd(&g_cnt[b], 0u) < (unsigned)CHUNKS) { }
        __threadfence();                  // acquire the slot values
        const unsigned long long pk = __ldcg(&g_pack[b * N_CLS + k]);
        const float sum             = __ldcg(&g_sum [b * N_CLS + k]);
        s_arg  = N_POS - 1 - (int)(unsigned)(pk & 0xffffffffu);
        s_mask = (sum * (1.0f / N_POS) > TAU) ? 1.0f : 0.0f;
    }
    __syncthreads();

    // ---------------- Gather emb[b, arg, :] * mask ----------------
    const float4* __restrict__ src =
        (const float4*)(emb + ((size_t)b * N_POS + (size_t)s_arg) * C_DIM);
    float4* __restrict__ dst =
        (float4*)(out + ((size_t)b * N_CLS + (size_t)k) * C_DIM);

    const float m = s_mask;
    float4 v0 = __ldg(src + t);
    float4 v1 = __ldg(src + t + NTHREADS);
    v0.x *= m; v0.y *= m; v0.z *= m; v0.w *= m;
    v1.x *= m; v1.y *= m; v1.z *= m; v1.w *= m;
    dst[t]            = v0;
    dst[t + NTHREADS] = v1;

    // ---------------- Replay-safe reset by last gather block ----------------
    __syncthreads();
    if (t == 0) {
        const unsigned d = atomicAdd(&g_done, 1u);
        const unsigned ngather = (gridDim.x / CHUNKS) * N_CLS;   // B*8
        if (d == ngather - 1u) {          // every reader has finished
            #pragma unroll
            for (int i = 0; i < MAX_B * N_CLS; ++i) {
                g_pack[i] = 0ULL;
                g_sum[i]  = 0.0f;
            }
            #pragma unroll
            for (int i = 0; i < MAX_B; ++i) g_cnt[i] = 0u;
            g_done = 0u;
            __threadfence();
        }
    }
}

extern "C" void kernel_launch(void* const* d_in, const int* in_sizes, int n_in,
                              void* d_out, int out_size)
{
    const float* emb  = (const float*)d_in[0];
    const float* prob = (const float*)d_in[1];
    float* out = (float*)d_out;

    const int B = in_sizes[0] / (N_POS * C_DIM);   // = 2

    mfbd_fused<<<B * CHUNKS, NTHREADS>>>(emb, prob, out);   // 128 blocks, 1 wave
}

// round 8
// speedup vs baseline: 1.2620x; 1.2399x over previous
#include <cuda_runtime.h>
#include <cstdint>

// MaxFeatBlockDescriptorLayer, fused single launch, flagged-slot handoff:
//   128 blocks; block (b,chunk) reduces 256 positions x 8 classes of prob
//   in registers (thread = position, warp shuffle per class, ballot for
//   first-index ties), combines 8 warps via an 8x8 smem tile, and publishes
//   ONE 16B slot per (b,class,chunk): {pack, sum, flag} with a single
//   st.global.cg.v4 (data+flag reach L2 atomically, compiler-fenced).
//   Blocks with chunk<8 also gather: warp 0 polls its class's 64 slots with
//   ld.global.cg.v4 ("memory"-clobbered so the block's own producer store
//   can NOT be sunk past the poll -- R6's deadlock). When flags show, the
//   values are already in registers: reduce, reset own slots (replay-safe),
//   then 256 threads gather emb[b, argmax, :] * mask.
//
// argmax tie-break = first index: ballot lowest lane in-warp; packed
// (bits(v)<<32)|(N_POS-1-idx) max across warps/chunks (prob >= 0 so float
// bits are order-monotonic).

#define N_POS    16384
#define N_CLS    8
#define C_DIM    2048
#define TAU      0.3f
#define CHUNKS   64
#define POS_PC   (N_POS / CHUNKS)        // 256
#define NTHREADS 256
#define MAX_B    8

// 16B slot: .x = pack lo, .y = pack hi, .z = sum bits, .w = flag
__device__ uint4 g_slot[MAX_B * N_CLS * CHUNKS];

__device__ __forceinline__ void slot_store(uint4* p, uint4 v) {
    asm volatile("st.global.cg.v4.u32 [%0], {%1,%2,%3,%4};"
                 :: "l"(p), "r"(v.x), "r"(v.y), "r"(v.z), "r"(v.w)
                 : "memory");
}
__device__ __forceinline__ uint4 slot_load(const uint4* p) {
    uint4 r;
    asm volatile("ld.global.cg.v4.u32 {%0,%1,%2,%3}, [%4];"
                 : "=r"(r.x), "=r"(r.y), "=r"(r.z), "=r"(r.w)
                 : "l"(p) : "memory");
    return r;
}

__global__ __launch_bounds__(NTHREADS)
void mfbd_fused(const float* __restrict__ emb,
                const float* __restrict__ prob,
                float* __restrict__ out)
{
    const int t    = threadIdx.x;
    const int w    = t >> 5;
    const int lane = t & 31;

    const int b     = blockIdx.x / CHUNKS;
    const int chunk = blockIdx.x % CHUNKS;

    __shared__ unsigned long long s_pk[N_CLS][N_CLS];   // [src warp][class]
    __shared__ float              s_sm[N_CLS][N_CLS];
    __shared__ int   s_arg;
    __shared__ float s_mask;

    // ---------------- Phase 1: thread = one position, regs only ----------------
    const float4* __restrict__ p4 =
        (const float4*)(prob + ((size_t)b * N_POS + (size_t)chunk * POS_PC) * N_CLS);
    const float4 a0 = __ldg(p4 + 2 * t);
    const float4 a1 = __ldg(p4 + 2 * t + 1);
    const float v[8] = { a0.x, a0.y, a0.z, a0.w, a1.x, a1.y, a1.z, a1.w };

    unsigned long long my_pk = 0ULL;
    float              my_sum = 0.0f;

    #pragma unroll
    for (int c = 0; c < N_CLS; ++c) {
        float m = v[c];
        float s = v[c];
        #pragma unroll
        for (int off = 16; off > 0; off >>= 1) {
            m = fmaxf(m, __shfl_xor_sync(0xffffffffu, m, off));
            s += __shfl_xor_sync(0xffffffffu, s, off);
        }
        const unsigned bal = __ballot_sync(0xffffffffu, v[c] == m);
        const int src  = __ffs(bal) - 1;                    // lowest lane = first idx
        const int gidx = chunk * POS_PC + w * 32 + src;
        if (lane == c) {
            my_pk  = ((unsigned long long)__float_as_uint(m) << 32)
                   | (unsigned)(N_POS - 1 - gidx);
            my_sum = s;
        }
    }
    if (lane < N_CLS) {
        s_pk[w][lane] = my_pk;
        s_sm[w][lane] = my_sum;
    }
    __syncthreads();

    // ---- combine 8 warp-partials per class: warp w -> class w, lanes 0..7 ----
    if (lane < N_CLS) {
        unsigned long long pk = s_pk[lane][w];
        float s = s_sm[lane][w];
        #pragma unroll
        for (int off = 4; off > 0; off >>= 1) {
            const unsigned long long o = __shfl_xor_sync(0xffu, pk, off);
            pk = pk > o ? pk : o;
            s += __shfl_xor_sync(0xffu, s, off);
        }
        if (lane == 0) {
            uint4 sl;
            sl.x = (unsigned)(pk & 0xffffffffu);
            sl.y = (unsigned)(pk >> 32);
            sl.z = __float_as_uint(s);
            sl.w = 1u;                                       // flag
            slot_store(&g_slot[(b * N_CLS + w) * CHUNKS + chunk], sl);
        }
    }

    // ---------------- Gather blocks: chunk < 8 -> class k = chunk ----------------
    if (chunk >= N_CLS) return;
    const int k = chunk;

    if (w == 0) {
        uint4* const base = &g_slot[(b * N_CLS + k) * CHUNKS];
        uint4 r0, r1;
        for (;;) {
            r0 = slot_load(base + lane);
            r1 = slot_load(base + lane + 32);
            if (__all_sync(0xffffffffu, (r0.w & r1.w) != 0u)) break;
            __nanosleep(64);
        }
        const unsigned long long p0 = ((unsigned long long)r0.y << 32) | r0.x;
        const unsigned long long p1 = ((unsigned long long)r1.y << 32) | r1.x;
        unsigned long long pk = p0 > p1 ? p0 : p1;
        float s = __uint_as_float(r0.z) + __uint_as_float(r1.z);
        #pragma unroll
        for (int off = 16; off > 0; off >>= 1) {
            const unsigned long long o = __shfl_xor_sync(0xffffffffu, pk, off);
            pk = pk > o ? pk : o;
            s += __shfl_xor_sync(0xffffffffu, s, off);
        }
        if (lane == 0) {
            s_arg  = N_POS - 1 - (int)(unsigned)(pk & 0xffffffffu);
            s_mask = (s * (1.0f / N_POS) > TAU) ? 1.0f : 0.0f;
        }
        // replay-safe reset: this block is the sole reader of these slots
        // (ordered after the poll by the "memory" clobbers above)
        const uint4 z = make_uint4(0u, 0u, 0u, 0u);
        slot_store(base + lane,      z);
        slot_store(base + lane + 32, z);
    }
    __syncthreads();

    // ---------------- Gather emb[b, arg, :] * mask ----------------
    const float4* __restrict__ src =
        (const float4*)(emb + ((size_t)b * N_POS + (size_t)s_arg) * C_DIM);
    float4* __restrict__ dst =
        (float4*)(out + ((size_t)b * N_CLS + (size_t)k) * C_DIM);

    const float m = s_mask;
    float4 v0 = __ldg(src + t);
    float4 v1 = __ldg(src + t + NTHREADS);
    v0.x *= m; v0.y *= m; v0.z *= m; v0.w *= m;
    v1.x *= m; v1.y *= m; v1.z *= m; v1.w *= m;
    dst[t]            = v0;
    dst[t + NTHREADS] = v1;
}

extern "C" void kernel_launch(void* const* d_in, const int* in_sizes, int n_in,
                              void* d_out, int out_size)
{
    const float* emb  = (const float*)d_in[0];
    const float* prob = (const float*)d_in[1];
    float* out = (float*)d_out;

    const int B = in_sizes[0] / (N_POS * C_DIM);   // = 2

    mfbd_fused<<<B * CHUNKS, NTHREADS>>>(emb, prob, out);   // 128 blocks, 1 wave
}